// round 3
// baseline (speedup 1.0000x reference)
#include <cuda_runtime.h>
#include <cuda_bf16.h>
#include <math.h>

// ---------------------------------------------------------------------------
// MLA forward, fp32 baseline.
// Shapes: B=1, S=2048, HIDDEN=7168, NH=32, DQ=1536, DKV=512, DH=128, DR=64
// ---------------------------------------------------------------------------

#define S_LEN   2048
#define HIDDEN  7168
#define NH      32
#define DQ      1536
#define DKV     512
#define DH      128
#define DR      64
#define DQR     (DH + DR)            // 192
#define NQCR    (NH * DQR)           // 6144
#define NKV     (NH * 2 * DH)        // 8192
#define DCKV    (DKV + DR)           // 576
#define NODIM   (NH * DH)            // 4096

// Scratch (device globals; no allocation allowed)
__device__ float g_cq   [(long long)S_LEN * DQ];          // 2048 x 1536
__device__ float g_qcr  [(long long)S_LEN * NQCR];        // 2048 x 6144
__device__ float g_ckv  [(long long)S_LEN * DCKV];        // 2048 x 576
__device__ float g_kv   [(long long)S_LEN * NKV];         // 2048 x 8192
__device__ float g_kT   [(long long)NH * DQR * S_LEN];    // [h][d][s] 32x192x2048
__device__ float g_sc   [(long long)NH * S_LEN * S_LEN];  // [h][q][k] 512 MiB
__device__ float g_o    [(long long)S_LEN * NODIM];       // 2048 x 4096

// ---------------------------------------------------------------------------
// Generic batched SGEMM: C[m][n] = alpha * sum_k A[m][k]*B[k][n]
// 128x128 block tile, BK=16, 256 threads, 8x8 per thread.
// Requires: K % 16 == 0, N % 4 == 0, lda/ldb % 4 == 0 (all call sites satisfy).
// ---------------------------------------------------------------------------
__global__ __launch_bounds__(256)
void sgemm128(int M, int N, int K,
              const float* __restrict__ A, int lda, long long sA,
              const float* __restrict__ B, int ldb, long long sB,
              float* __restrict__ C, int ldc, long long sC,
              float alpha)
{
    __shared__ float As[16][128];
    __shared__ float Bs[16][128];

    const float* Ab = A + (long long)blockIdx.z * sA;
    const float* Bb = B + (long long)blockIdx.z * sB;
    float*       Cb = C + (long long)blockIdx.z * sC;

    const int bm = blockIdx.y * 128;
    const int bn = blockIdx.x * 128;
    const int tid = threadIdx.x;
    const int tx = tid & 15;
    const int ty = tid >> 4;

    float acc[8][8];
#pragma unroll
    for (int i = 0; i < 8; i++)
#pragma unroll
        for (int j = 0; j < 8; j++) acc[i][j] = 0.f;

    for (int k0 = 0; k0 < K; k0 += 16) {
        // Load A tile (transposed into As[k][m])
#pragma unroll
        for (int r = 0; r < 2; r++) {
            int e  = tid + r * 256;          // 0..511, each = one float4
            int m  = e >> 2;                 // 0..127
            int kq = (e & 3) << 2;           // 0,4,8,12
            float4 v = make_float4(0.f, 0.f, 0.f, 0.f);
            int gm = bm + m;
            if (gm < M)
                v = *(const float4*)(Ab + (long long)gm * lda + (k0 + kq));
            As[kq + 0][m] = v.x;
            As[kq + 1][m] = v.y;
            As[kq + 2][m] = v.z;
            As[kq + 3][m] = v.w;
        }
        // Load B tile
#pragma unroll
        for (int r = 0; r < 2; r++) {
            int e  = tid + r * 256;
            int kk = e >> 5;                 // 0..15
            int nq = (e & 31) << 2;          // 0..124
            float4 v = make_float4(0.f, 0.f, 0.f, 0.f);
            int gn = bn + nq;
            if (gn < N)
                v = *(const float4*)(Bb + (long long)(k0 + kk) * ldb + gn);
            *(float4*)&Bs[kk][nq] = v;
        }
        __syncthreads();

#pragma unroll
        for (int kk = 0; kk < 16; kk++) {
            float a[8], b[8];
            *(float4*)&a[0] = *(const float4*)&As[kk][ty * 8];
            *(float4*)&a[4] = *(const float4*)&As[kk][ty * 8 + 4];
            *(float4*)&b[0] = *(const float4*)&Bs[kk][tx * 8];
            *(float4*)&b[4] = *(const float4*)&Bs[kk][tx * 8 + 4];
#pragma unroll
            for (int i = 0; i < 8; i++)
#pragma unroll
                for (int j = 0; j < 8; j++)
                    acc[i][j] = fmaf(a[i], b[j], acc[i][j]);
        }
        __syncthreads();
    }

#pragma unroll
    for (int i = 0; i < 8; i++) {
        int gm = bm + ty * 8 + i;
        if (gm >= M) continue;
#pragma unroll
        for (int j = 0; j < 8; j++) {
            int gn = bn + tx * 8 + j;
            if (gn < N)
                Cb[(long long)gm * ldc + gn] = alpha * acc[i][j];
        }
    }
}

// ---------------------------------------------------------------------------
// RMSNorm in place over first W columns of each row (row stride ld).
// One block per row. eps matches jnp.finfo(float32).eps.
// ---------------------------------------------------------------------------
__global__ void rmsnorm_kernel(float* __restrict__ x, const float* __restrict__ g,
                               int W, int ld)
{
    __shared__ float red[32];
    float* row = x + (long long)blockIdx.x * ld;
    float s = 0.f;
    for (int i = threadIdx.x; i < W; i += blockDim.x) {
        float v = row[i];
        s += v * v;
    }
#pragma unroll
    for (int o = 16; o; o >>= 1) s += __shfl_xor_sync(0xffffffffu, s, o);
    int w = threadIdx.x >> 5, l = threadIdx.x & 31;
    if (l == 0) red[w] = s;
    __syncthreads();
    if (w == 0) {
        float t = (l < (blockDim.x >> 5)) ? red[l] : 0.f;
#pragma unroll
        for (int o = 16; o; o >>= 1) t += __shfl_xor_sync(0xffffffffu, t, o);
        if (l == 0) red[0] = t;
    }
    __syncthreads();
    float scale = rsqrtf(red[0] / (float)W + 1.1920929e-07f);
    for (int i = threadIdx.x; i < W; i += blockDim.x)
        row[i] = row[i] * scale * g[i];
}

// ---------------------------------------------------------------------------
// RoPE (D=64). For lane j<32 with pair (j, j+32):
//   out[j]    = x[j]*cos - x[j+32]*sin
//   out[j+32] = x[j+32]*cos + x[j]*sin
// with freq = t / ROPE_BASE^(2j/64).
// ---------------------------------------------------------------------------
__device__ __forceinline__ void rope_pair(float* base, int j, int t)
{
    float ex  = (2.0f * (float)j) / 64.0f;
    float inv = 1.0f / powf(10000.0f, ex);
    float fr  = (float)t * inv;
    float c   = cosf(fr);
    float sn  = sinf(fr);
    float x1 = base[j];
    float x2 = base[j + 32];
    base[j]      = x1 * c - x2 * sn;
    base[j + 32] = x2 * c + x1 * sn;
}

// One warp per (s, h) item; ropes qcr[s, h*192+128 .. +191]
__global__ void rope_q_kernel(float* __restrict__ qcr)
{
    int item = blockIdx.x * (blockDim.x >> 5) + (threadIdx.x >> 5);
    if (item >= S_LEN * NH) return;
    int s = item >> 5;       // item / 32
    int h = item & 31;
    int j = threadIdx.x & 31;
    float* base = qcr + (long long)s * NQCR + h * DQR + DH;
    rope_pair(base, j, s);
}

// One warp per s; ropes ckv[s, 512..575]
__global__ void rope_k_kernel(float* __restrict__ ckv)
{
    int item = blockIdx.x * (blockDim.x >> 5) + (threadIdx.x >> 5);
    if (item >= S_LEN) return;
    int j = threadIdx.x & 31;
    float* base = ckv + (long long)item * DCKV + DKV;
    rope_pair(base, j, item);
}

// ---------------------------------------------------------------------------
// Build K^T buffer: kT[h][d][s] = (d<128) ? kv[s, h*256+d] : ckv[s, 512+d-128]
// ---------------------------------------------------------------------------
__global__ void build_kT_kernel(const float* __restrict__ kv,
                                const float* __restrict__ ckv,
                                float* __restrict__ kT)
{
    const long long total = (long long)NH * DQR * S_LEN;
    for (long long i = (long long)blockIdx.x * blockDim.x + threadIdx.x;
         i < total; i += (long long)gridDim.x * blockDim.x) {
        int s = (int)(i % S_LEN);
        long long t = i / S_LEN;
        int d = (int)(t % DQR);
        int h = (int)(t / DQR);
        float v;
        if (d < DH) v = kv[(long long)s * NKV + h * 2 * DH + d];
        else        v = ckv[(long long)s * DCKV + DKV + (d - DH)];
        kT[i] = v;
    }
}

// ---------------------------------------------------------------------------
// Row softmax in place (width 2048), one block per row.
// ---------------------------------------------------------------------------
__global__ void softmax_kernel(float* __restrict__ sc)
{
    __shared__ float red[32];
    float* row = sc + (long long)blockIdx.x * S_LEN;
    int w = threadIdx.x >> 5, l = threadIdx.x & 31;

    // max
    float m = -3.402823466e+38f;
    for (int i = threadIdx.x; i < S_LEN; i += blockDim.x)
        m = fmaxf(m, row[i]);
#pragma unroll
    for (int o = 16; o; o >>= 1) m = fmaxf(m, __shfl_xor_sync(0xffffffffu, m, o));
    if (l == 0) red[w] = m;
    __syncthreads();
    if (w == 0) {
        float t = (l < (blockDim.x >> 5)) ? red[l] : -3.402823466e+38f;
#pragma unroll
        for (int o = 16; o; o >>= 1) t = fmaxf(t, __shfl_xor_sync(0xffffffffu, t, o));
        if (l == 0) red[0] = t;
    }
    __syncthreads();
    float M = red[0];
    __syncthreads();

    // exp + sum
    float s = 0.f;
    for (int i = threadIdx.x; i < S_LEN; i += blockDim.x) {
        float e = expf(row[i] - M);
        row[i] = e;
        s += e;
    }
#pragma unroll
    for (int o = 16; o; o >>= 1) s += __shfl_xor_sync(0xffffffffu, s, o);
    if (l == 0) red[w] = s;
    __syncthreads();
    if (w == 0) {
        float t = (l < (blockDim.x >> 5)) ? red[l] : 0.f;
#pragma unroll
        for (int o = 16; o; o >>= 1) t += __shfl_xor_sync(0xffffffffu, t, o);
        if (l == 0) red[0] = t;
    }
    __syncthreads();
    float inv = 1.0f / red[0];
    for (int i = threadIdx.x; i < S_LEN; i += blockDim.x)
        row[i] *= inv;
}

// ---------------------------------------------------------------------------
// Launch
// ---------------------------------------------------------------------------
extern "C" void kernel_launch(void* const* d_in, const int* in_sizes, int n_in,
                              void* d_out, int out_size)
{
    const float* X     = (const float*)d_in[0];   // [2048, 7168]
    const float* W_dq  = (const float*)d_in[1];   // [7168, 1536]
    const float* gq    = (const float*)d_in[2];   // [1536]
    const float* W_uq  = (const float*)d_in[3];   // [1536, 6144]
    const float* W_dkv = (const float*)d_in[4];   // [7168, 576]
    const float* gkv   = (const float*)d_in[5];   // [512]
    const float* W_ukv = (const float*)d_in[6];   // [512, 8192]
    const float* W_o   = (const float*)d_in[7];   // [4096, 7168]
    float* out = (float*)d_out;                   // [2048, 7168]

    float *cq, *qcr, *ckv, *kv, *kT, *sc, *ob;
    cudaGetSymbolAddress((void**)&cq,  g_cq);
    cudaGetSymbolAddress((void**)&qcr, g_qcr);
    cudaGetSymbolAddress((void**)&ckv, g_ckv);
    cudaGetSymbolAddress((void**)&kv,  g_kv);
    cudaGetSymbolAddress((void**)&kT,  g_kT);
    cudaGetSymbolAddress((void**)&sc,  g_sc);
    cudaGetSymbolAddress((void**)&ob,  g_o);

    dim3 blk(256);

    // G1: c_q = X @ W_dq   [2048 x 1536], K=7168
    sgemm128<<<dim3(DQ / 128, S_LEN / 128, 1), blk>>>(
        S_LEN, DQ, HIDDEN, X, HIDDEN, 0, W_dq, DQ, 0, cq, DQ, 0, 1.0f);

    // rmsnorm(c_q, g_q) in place
    rmsnorm_kernel<<<S_LEN, 256>>>(cq, gq, DQ, DQ);

    // G2: qcr = c_qn @ W_uq   [2048 x 6144], K=1536
    sgemm128<<<dim3(NQCR / 128, S_LEN / 128, 1), blk>>>(
        S_LEN, NQCR, DQ, cq, DQ, 0, W_uq, NQCR, 0, qcr, NQCR, 0, 1.0f);

    // RoPE on q_r slices of qcr
    rope_q_kernel<<<(S_LEN * NH) / 8, 256>>>(qcr);

    // G3: ckv_kr = X @ W_dkv   [2048 x 576], K=7168
    sgemm128<<<dim3((DCKV + 127) / 128, S_LEN / 128, 1), blk>>>(
        S_LEN, DCKV, HIDDEN, X, HIDDEN, 0, W_dkv, DCKV, 0, ckv, DCKV, 0, 1.0f);

    // rmsnorm on first 512 cols of ckv
    rmsnorm_kernel<<<S_LEN, 256>>>(ckv, gkv, DKV, DCKV);

    // RoPE on k_r (cols 512..575 of ckv)
    rope_k_kernel<<<S_LEN / 8, 256>>>(ckv);

    // G4: kv = ckv_n @ W_ukv   [2048 x 8192], K=512
    sgemm128<<<dim3(NKV / 128, S_LEN / 128, 1), blk>>>(
        S_LEN, NKV, DKV, ckv, DCKV, 0, W_ukv, NKV, 0, kv, NKV, 0, 1.0f);

    // Build K^T [h][d][s]
    build_kT_kernel<<<4096, 256>>>(kv, ckv, kT);

    // G5: scores[h] = Q[h] @ K[h]^T * scale   (batched over 32 heads)
    // A: qcr + h*192 (lda 6144), B: kT[h] (192x2048, ldb 2048)
    float scale = 1.0f / sqrtf((float)DQR);
    sgemm128<<<dim3(S_LEN / 128, S_LEN / 128, NH), blk>>>(
        S_LEN, S_LEN, DQR,
        qcr, NQCR, (long long)DQR,
        kT, S_LEN, (long long)DQR * S_LEN,
        sc, S_LEN, (long long)S_LEN * S_LEN,
        scale);

    // softmax rows
    softmax_kernel<<<NH * S_LEN, 256>>>(sc);

    // G6: O[s, h*128+d] = P[h] @ V[h]   (batched)
    // B: kv + h*256 + 128 (ldb 8192), C: g_o + h*128 (ldc 4096)
    sgemm128<<<dim3(1, S_LEN / 128, NH), blk>>>(
        S_LEN, DH, S_LEN,
        sc, S_LEN, (long long)S_LEN * S_LEN,
        kv + DH, NKV, (long long)2 * DH,
        ob, NODIM, (long long)DH,
        1.0f);

    // G7: out = O @ W_o   [2048 x 7168], K=4096
    sgemm128<<<dim3(HIDDEN / 128, S_LEN / 128, 1), blk>>>(
        S_LEN, HIDDEN, NODIM, ob, NODIM, 0, W_o, HIDDEN, 0, out, HIDDEN, 0, 1.0f);
}

// round 5
// speedup vs baseline: 1.2247x; 1.2247x over previous
#include <cuda_runtime.h>
#include <cuda_bf16.h>
#include <math.h>
#include <stdint.h>
#include <cstdint>

// ---------------------------------------------------------------------------
// MLA forward — bf16x3 (hi/lo split) tensor-core GEMMs via mma.sync.m16n8k16.
// Shapes: B=1, S=2048, HIDDEN=7168, NH=32, DQ=1536, DKV=512, DH=128, DR=64
// ---------------------------------------------------------------------------

#define S_LEN   2048
#define HIDDEN  7168
#define NH      32
#define DQ      1536
#define DKV     512
#define DH      128
#define DR      64
#define DQR     (DH + DR)            // 192
#define NQCR    (NH * DQR)           // 6144
#define NKV     (NH * 2 * DH)        // 8192
#define DCKV    (DKV + DR)           // 576
#define NODIM   (NH * DH)            // 4096

typedef __nv_bfloat16 bf16;
typedef __nv_bfloat162 bf162;

// ---------------- scratch (device globals; no allocation allowed) ----------
__device__ float g_cq [(long long)S_LEN * DQ];
__device__ float g_qcr[(long long)S_LEN * NQCR];
__device__ float g_ckv[(long long)S_LEN * DCKV];
__device__ float g_kv [(long long)S_LEN * NKV];
__device__ float g_sc [(long long)NH * S_LEN * S_LEN];
__device__ float g_o  [(long long)S_LEN * NODIM];

__device__ bf16 g_Xh [(long long)S_LEN * HIDDEN],  g_Xl [(long long)S_LEN * HIDDEN];
__device__ bf16 g_Wdqh[(long long)HIDDEN * DQ],    g_Wdql[(long long)HIDDEN * DQ];
__device__ bf16 g_Wuqh[(long long)DQ * NQCR],      g_Wuql[(long long)DQ * NQCR];
__device__ bf16 g_Wdkvh[(long long)HIDDEN * DCKV], g_Wdkvl[(long long)HIDDEN * DCKV];
__device__ bf16 g_Wukvh[(long long)DKV * NKV],     g_Wukvl[(long long)DKV * NKV];
__device__ bf16 g_Woh [(long long)NODIM * HIDDEN], g_Wol [(long long)NODIM * HIDDEN];
__device__ bf16 g_cqh [(long long)S_LEN * DQ],     g_cql [(long long)S_LEN * DQ];
__device__ bf16 g_qh  [(long long)S_LEN * NQCR],   g_ql  [(long long)S_LEN * NQCR];
__device__ bf16 g_ckvh[(long long)S_LEN * DCKV],   g_ckvl[(long long)S_LEN * DCKV];
__device__ bf16 g_kvh [(long long)S_LEN * NKV],    g_kvl [(long long)S_LEN * NKV];
__device__ bf16 g_kTh [(long long)NH * DQR * S_LEN], g_kTl[(long long)NH * DQR * S_LEN];
__device__ bf16 g_Ph  [(long long)NH * S_LEN * S_LEN], g_Pl[(long long)NH * S_LEN * S_LEN];
__device__ bf16 g_oh  [(long long)S_LEN * NODIM],  g_ol [(long long)S_LEN * NODIM];

// ---------------------------------------------------------------------------
__device__ __forceinline__ void split2(float v, bf16& h, bf16& l)
{
    bf16 hh = __float2bfloat16(v);         // RN
    h = hh;
    l = __float2bfloat16(v - __bfloat162float(hh));   // exact residual
}

// fp32 -> (hi, lo) bf16 split, vectorized. n % 4 == 0 at all call sites.
__global__ void split_kernel(const float* __restrict__ s,
                             bf16* __restrict__ h, bf16* __restrict__ l,
                             long long n)
{
    for (long long i = ((long long)blockIdx.x * blockDim.x + threadIdx.x) * 4;
         i < n; i += (long long)gridDim.x * blockDim.x * 4) {
        float4 v = *(const float4*)(s + i);
        bf16 h0,h1,h2,h3,l0,l1,l2,l3;
        split2(v.x,h0,l0); split2(v.y,h1,l1); split2(v.z,h2,l2); split2(v.w,h3,l3);
        *(bf162*)(h + i)     = __halves2bfloat162(h0, h1);
        *(bf162*)(h + i + 2) = __halves2bfloat162(h2, h3);
        *(bf162*)(l + i)     = __halves2bfloat162(l0, l1);
        *(bf162*)(l + i + 2) = __halves2bfloat162(l2, l3);
    }
}

// ---------------------------------------------------------------------------
// Batched GEMM, bf16x3 compensated: C = alpha * (Ah+Al)(Bh+Bl) (drop Al*Bl).
// Block tile 128x128, BK=16, 256 threads, 8 warps of 32x64.
// A global: [M][K] row-major (k contig), hi/lo. B global: [K][N] (n contig).
// Requires: K%16==0, M%128==0, N even, lda%8==0, base offsets %8==0.
// ---------------------------------------------------------------------------
#define MMA_OP(ac, a, b)                                                     \
    asm volatile("mma.sync.aligned.m16n8k16.row.col.f32.bf16.bf16.f32 "      \
        "{%0,%1,%2,%3}, {%4,%5,%6,%7}, {%8,%9}, {%0,%1,%2,%3};"              \
        : "+f"((ac)[0]), "+f"((ac)[1]), "+f"((ac)[2]), "+f"((ac)[3])         \
        : "r"((a)[0]), "r"((a)[1]), "r"((a)[2]), "r"((a)[3]),                \
          "r"((b)[0]), "r"((b)[1]))

__global__ __launch_bounds__(256, 1)
void bgemm3(int M, int N, int K,
            const bf16* __restrict__ Ah, const bf16* __restrict__ Al,
            int lda, long long sA,
            const bf16* __restrict__ Bh, const bf16* __restrict__ Bl,
            int ldb, long long sB,
            float* __restrict__ C, int ldc, long long sC, float alpha)
{
    __shared__ bf16 AsH[128][24];   // [m][k], 8-elem pad
    __shared__ bf16 AsL[128][24];
    __shared__ bf16 BsH[128][24];   // [n][k], 8-elem pad
    __shared__ bf16 BsL[128][24];

    const bf16* pAh = Ah + (long long)blockIdx.z * sA;
    const bf16* pAl = Al + (long long)blockIdx.z * sA;
    const bf16* pBh = Bh + (long long)blockIdx.z * sB;
    const bf16* pBl = Bl + (long long)blockIdx.z * sB;
    float*      pC  = C  + (long long)blockIdx.z * sC;

    const int tid = threadIdx.x;
    const int bm = blockIdx.y << 7;
    const int bn = blockIdx.x << 7;

    // loader indices
    const int la_m = tid >> 1;              // 0..127
    const int la_k = (tid & 1) << 3;        // 0, 8
    const int lb_n = (tid & 63) << 1;       // 0..126 even
    const int lb_k = tid >> 6;              // 0..3

    // compute indices
    const int lane = tid & 31;
    const int warp = tid >> 5;
    const int wm = (warp & 3) << 5;         // 0..96
    const int wn = (warp >> 2) << 6;        // 0, 64
    const int g  = lane >> 2;
    const int qt = (lane & 3) << 1;

    float acc[2][8][4];
#pragma unroll
    for (int i = 0; i < 2; i++)
#pragma unroll
        for (int j = 0; j < 8; j++)
#pragma unroll
            for (int c = 0; c < 4; c++) acc[i][j][c] = 0.f;

    uint4 stAh, stAl;
    uint32_t stBh[4], stBl[4];
    const int nk = K >> 4;

    // ---- prologue: load k-tile 0 into staging regs ----
    {
        const long long aoff = (long long)(bm + la_m) * lda + la_k;
        stAh = *(const uint4*)(pAh + aoff);
        stAl = *(const uint4*)(pAl + aoff);
        const int gn = bn + lb_n;
#pragma unroll
        for (int r = 0; r < 4; r++) {
            const int kk = lb_k + (r << 2);
            if (gn < N) {
                const long long boff = (long long)kk * ldb + gn;
                stBh[r] = *(const uint32_t*)(pBh + boff);
                stBl[r] = *(const uint32_t*)(pBl + boff);
            } else { stBh[r] = 0u; stBl[r] = 0u; }
        }
    }
    // ---- store staging -> smem ----
    {
        *(uint4*)&AsH[la_m][la_k] = stAh;
        *(uint4*)&AsL[la_m][la_k] = stAl;
#pragma unroll
        for (int r = 0; r < 4; r++) {
            const int kk = lb_k + (r << 2);
            bf162 vh = *(bf162*)&stBh[r];
            bf162 vl = *(bf162*)&stBl[r];
            BsH[lb_n][kk] = vh.x;  BsH[lb_n + 1][kk] = vh.y;
            BsL[lb_n][kk] = vl.x;  BsL[lb_n + 1][kk] = vl.y;
        }
    }
    __syncthreads();

    for (int kt = 0; kt < nk; kt++) {
        // prefetch next tile into registers (hidden under compute)
        if (kt + 1 < nk) {
            const int k0 = (kt + 1) << 4;
            const long long aoff = (long long)(bm + la_m) * lda + k0 + la_k;
            stAh = *(const uint4*)(pAh + aoff);
            stAl = *(const uint4*)(pAl + aoff);
            const int gn = bn + lb_n;
#pragma unroll
            for (int r = 0; r < 4; r++) {
                const int kk = k0 + lb_k + (r << 2);
                if (gn < N) {
                    const long long boff = (long long)kk * ldb + gn;
                    stBh[r] = *(const uint32_t*)(pBh + boff);
                    stBl[r] = *(const uint32_t*)(pBl + boff);
                } else { stBh[r] = 0u; stBl[r] = 0u; }
            }
        }

        uint32_t af[2][4];
        uint32_t bfr[8][2];

        // Ah fragments
#pragma unroll
        for (int im = 0; im < 2; im++) {
            const int r0 = wm + (im << 4) + g;
            af[im][0] = *(const uint32_t*)&AsH[r0][qt];
            af[im][1] = *(const uint32_t*)&AsH[r0 + 8][qt];
            af[im][2] = *(const uint32_t*)&AsH[r0][qt + 8];
            af[im][3] = *(const uint32_t*)&AsH[r0 + 8][qt + 8];
        }
        // Bh fragments
#pragma unroll
        for (int jn = 0; jn < 8; jn++) {
            const int cc = wn + (jn << 3) + g;
            bfr[jn][0] = *(const uint32_t*)&BsH[cc][qt];
            bfr[jn][1] = *(const uint32_t*)&BsH[cc][qt + 8];
        }
        // pass 1: Ah * Bh
#pragma unroll
        for (int im = 0; im < 2; im++)
#pragma unroll
            for (int jn = 0; jn < 8; jn++) MMA_OP(acc[im][jn], af[im], bfr[jn]);

        // pass 2: Ah * Bl
#pragma unroll
        for (int jn = 0; jn < 8; jn++) {
            const int cc = wn + (jn << 3) + g;
            bfr[jn][0] = *(const uint32_t*)&BsL[cc][qt];
            bfr[jn][1] = *(const uint32_t*)&BsL[cc][qt + 8];
        }
#pragma unroll
        for (int im = 0; im < 2; im++)
#pragma unroll
            for (int jn = 0; jn < 8; jn++) MMA_OP(acc[im][jn], af[im], bfr[jn]);

        // pass 3: Al * Bh
#pragma unroll
        for (int im = 0; im < 2; im++) {
            const int r0 = wm + (im << 4) + g;
            af[im][0] = *(const uint32_t*)&AsL[r0][qt];
            af[im][1] = *(const uint32_t*)&AsL[r0 + 8][qt];
            af[im][2] = *(const uint32_t*)&AsL[r0][qt + 8];
            af[im][3] = *(const uint32_t*)&AsL[r0 + 8][qt + 8];
        }
#pragma unroll
        for (int jn = 0; jn < 8; jn++) {
            const int cc = wn + (jn << 3) + g;
            bfr[jn][0] = *(const uint32_t*)&BsH[cc][qt];
            bfr[jn][1] = *(const uint32_t*)&BsH[cc][qt + 8];
        }
#pragma unroll
        for (int im = 0; im < 2; im++)
#pragma unroll
            for (int jn = 0; jn < 8; jn++) MMA_OP(acc[im][jn], af[im], bfr[jn]);

        __syncthreads();
        if (kt + 1 < nk) {
            *(uint4*)&AsH[la_m][la_k] = stAh;
            *(uint4*)&AsL[la_m][la_k] = stAl;
#pragma unroll
            for (int r = 0; r < 4; r++) {
                const int kk = lb_k + (r << 2);
                bf162 vh = *(bf162*)&stBh[r];
                bf162 vl = *(bf162*)&stBl[r];
                BsH[lb_n][kk] = vh.x;  BsH[lb_n + 1][kk] = vh.y;
                BsL[lb_n][kk] = vl.x;  BsL[lb_n + 1][kk] = vl.y;
            }
            __syncthreads();
        }
    }

    // ---- epilogue ----
#pragma unroll
    for (int im = 0; im < 2; im++) {
#pragma unroll
        for (int jn = 0; jn < 8; jn++) {
            const int row = bm + wm + (im << 4) + g;
            const int col = bn + wn + (jn << 3) + qt;
            if (col < N) {
                *(float2*)(pC + (long long)row * ldc + col) =
                    make_float2(alpha * acc[im][jn][0], alpha * acc[im][jn][1]);
                *(float2*)(pC + (long long)(row + 8) * ldc + col) =
                    make_float2(alpha * acc[im][jn][2], alpha * acc[im][jn][3]);
            }
        }
    }
}

// ---------------------------------------------------------------------------
// RMSNorm in place over first W columns (row stride ld). One block per row.
// ---------------------------------------------------------------------------
__global__ void rmsnorm_kernel(float* __restrict__ x, const float* __restrict__ g,
                               int W, int ld)
{
    __shared__ float red[32];
    float* row = x + (long long)blockIdx.x * ld;
    float s = 0.f;
    for (int i = threadIdx.x; i < W; i += blockDim.x) {
        float v = row[i];
        s += v * v;
    }
#pragma unroll
    for (int o = 16; o; o >>= 1) s += __shfl_xor_sync(0xffffffffu, s, o);
    int w = threadIdx.x >> 5, l = threadIdx.x & 31;
    if (l == 0) red[w] = s;
    __syncthreads();
    if (w == 0) {
        float t = (l < (blockDim.x >> 5)) ? red[l] : 0.f;
#pragma unroll
        for (int o = 16; o; o >>= 1) t += __shfl_xor_sync(0xffffffffu, t, o);
        if (l == 0) red[0] = t;
    }
    __syncthreads();
    float scale = rsqrtf(red[0] / (float)W + 1.1920929e-07f);
    for (int i = threadIdx.x; i < W; i += blockDim.x)
        row[i] = row[i] * scale * g[i];
}

// ---------------------------------------------------------------------------
// RoPE (D=64)
// ---------------------------------------------------------------------------
__device__ __forceinline__ void rope_pair(float* base, int j, int t)
{
    float ex  = (2.0f * (float)j) / 64.0f;
    float inv = 1.0f / powf(10000.0f, ex);
    float fr  = (float)t * inv;
    float c   = cosf(fr);
    float sn  = sinf(fr);
    float x1 = base[j];
    float x2 = base[j + 32];
    base[j]      = x1 * c - x2 * sn;
    base[j + 32] = x2 * c + x1 * sn;
}

__global__ void rope_q_kernel(float* __restrict__ qcr)
{
    int item = blockIdx.x * (blockDim.x >> 5) + (threadIdx.x >> 5);
    if (item >= S_LEN * NH) return;
    int s = item >> 5;
    int h = item & 31;
    int j = threadIdx.x & 31;
    rope_pair(qcr + (long long)s * NQCR + h * DQR + DH, j, s);
}

__global__ void rope_k_kernel(float* __restrict__ ckv)
{
    int item = blockIdx.x * (blockDim.x >> 5) + (threadIdx.x >> 5);
    if (item >= S_LEN) return;
    int j = threadIdx.x & 31;
    rope_pair(ckv + (long long)item * DCKV + DKV, j, item);
}

// ---------------------------------------------------------------------------
// kT[h][d][s] split to hi/lo bf16 from fp32 kv + roped ckv.
// ---------------------------------------------------------------------------
__global__ void build_kT_split(const float* __restrict__ kv,
                               const float* __restrict__ ckv,
                               bf16* __restrict__ kTh, bf16* __restrict__ kTl)
{
    const long long total = (long long)NH * DQR * S_LEN;
    for (long long i = (long long)blockIdx.x * blockDim.x + threadIdx.x;
         i < total; i += (long long)gridDim.x * blockDim.x) {
        int s = (int)(i % S_LEN);
        long long t = i / S_LEN;
        int d = (int)(t % DQR);
        int h = (int)(t / DQR);
        float v;
        if (d < DH) v = kv[(long long)s * NKV + h * 2 * DH + d];
        else        v = ckv[(long long)s * DCKV + DKV + (d - DH)];
        bf16 hh, ll;
        split2(v, hh, ll);
        kTh[i] = hh;
        kTl[i] = ll;
    }
}

// ---------------------------------------------------------------------------
// Row softmax (width 2048) + bf16 hi/lo split output. One block per row.
// ---------------------------------------------------------------------------
__global__ void softmax_split_kernel(float* __restrict__ sc,
                                     bf16* __restrict__ ph, bf16* __restrict__ pl)
{
    __shared__ float red[32];
    float* row = sc + (long long)blockIdx.x * S_LEN;
    bf16* hrow = ph + (long long)blockIdx.x * S_LEN;
    bf16* lrow = pl + (long long)blockIdx.x * S_LEN;
    int w = threadIdx.x >> 5, l = threadIdx.x & 31;

    float m = -3.402823466e+38f;
    for (int i = threadIdx.x; i < S_LEN; i += blockDim.x)
        m = fmaxf(m, row[i]);
#pragma unroll
    for (int o = 16; o; o >>= 1) m = fmaxf(m, __shfl_xor_sync(0xffffffffu, m, o));
    if (l == 0) red[w] = m;
    __syncthreads();
    if (w == 0) {
        float t = (l < (blockDim.x >> 5)) ? red[l] : -3.402823466e+38f;
#pragma unroll
        for (int o = 16; o; o >>= 1) t = fmaxf(t, __shfl_xor_sync(0xffffffffu, t, o));
        if (l == 0) red[0] = t;
    }
    __syncthreads();
    float M = red[0];
    __syncthreads();

    float s = 0.f;
    for (int i = threadIdx.x; i < S_LEN; i += blockDim.x) {
        float e = expf(row[i] - M);
        row[i] = e;
        s += e;
    }
#pragma unroll
    for (int o = 16; o; o >>= 1) s += __shfl_xor_sync(0xffffffffu, s, o);
    if (l == 0) red[w] = s;
    __syncthreads();
    if (w == 0) {
        float t = (l < (blockDim.x >> 5)) ? red[l] : 0.f;
#pragma unroll
        for (int o = 16; o; o >>= 1) t += __shfl_xor_sync(0xffffffffu, t, o);
        if (l == 0) red[0] = t;
    }
    __syncthreads();
    float inv = 1.0f / red[0];
    for (int i = threadIdx.x; i < S_LEN; i += blockDim.x) {
        bf16 hh, ll;
        split2(row[i] * inv, hh, ll);
        hrow[i] = hh;
        lrow[i] = ll;
    }
}

// ---------------------------------------------------------------------------
static inline int split_grid(long long n)
{
    long long b = (n / 4 + 255) / 256;
    if (b > 8192) b = 8192;
    return (int)b;
}

extern "C" void kernel_launch(void* const* d_in, const int* in_sizes, int n_in,
                              void* d_out, int out_size)
{
    const float* X     = (const float*)d_in[0];
    const float* W_dq  = (const float*)d_in[1];
    const float* gq    = (const float*)d_in[2];
    const float* W_uq  = (const float*)d_in[3];
    const float* W_dkv = (const float*)d_in[4];
    const float* gkv   = (const float*)d_in[5];
    const float* W_ukv = (const float*)d_in[6];
    const float* W_o   = (const float*)d_in[7];
    float* out = (float*)d_out;

    float *cq, *qcr, *ckv, *kv, *sc, *ob;
    bf16 *Xh,*Xl,*Wdqh,*Wdql,*Wuqh,*Wuql,*Wdkvh,*Wdkvl,*Wukvh,*Wukvl,*Woh,*Wol;
    bf16 *cqh,*cql,*qh,*ql,*ckvh,*ckvl,*kvh,*kvl,*kTh,*kTl,*Ph,*Pl,*oh,*ol;

    cudaGetSymbolAddress((void**)&cq,  g_cq);
    cudaGetSymbolAddress((void**)&qcr, g_qcr);
    cudaGetSymbolAddress((void**)&ckv, g_ckv);
    cudaGetSymbolAddress((void**)&kv,  g_kv);
    cudaGetSymbolAddress((void**)&sc,  g_sc);
    cudaGetSymbolAddress((void**)&ob,  g_o);
    cudaGetSymbolAddress((void**)&Xh,  g_Xh);   cudaGetSymbolAddress((void**)&Xl,  g_Xl);
    cudaGetSymbolAddress((void**)&Wdqh, g_Wdqh);  cudaGetSymbolAddress((void**)&Wdql, g_Wdql);
    cudaGetSymbolAddress((void**)&Wuqh, g_Wuqh);  cudaGetSymbolAddress((void**)&Wuql, g_Wuql);
    cudaGetSymbolAddress((void**)&Wdkvh, g_Wdkvh); cudaGetSymbolAddress((void**)&Wdkvl, g_Wdkvl);
    cudaGetSymbolAddress((void**)&Wukvh, g_Wukvh); cudaGetSymbolAddress((void**)&Wukvl, g_Wukvl);
    cudaGetSymbolAddress((void**)&Woh, g_Woh);   cudaGetSymbolAddress((void**)&Wol, g_Wol);
    cudaGetSymbolAddress((void**)&cqh, g_cqh);   cudaGetSymbolAddress((void**)&cql, g_cql);
    cudaGetSymbolAddress((void**)&qh,  g_qh);    cudaGetSymbolAddress((void**)&ql,  g_ql);
    cudaGetSymbolAddress((void**)&ckvh, g_ckvh); cudaGetSymbolAddress((void**)&ckvl, g_ckvl);
    cudaGetSymbolAddress((void**)&kvh, g_kvh);   cudaGetSymbolAddress((void**)&kvl, g_kvl);
    cudaGetSymbolAddress((void**)&kTh, g_kTh);   cudaGetSymbolAddress((void**)&kTl, g_kTl);
    cudaGetSymbolAddress((void**)&Ph,  g_Ph);    cudaGetSymbolAddress((void**)&Pl,  g_Pl);
    cudaGetSymbolAddress((void**)&oh,  g_oh);    cudaGetSymbolAddress((void**)&ol,  g_ol);

    dim3 blk(256);

    // ---- split inputs to bf16 hi/lo ----
    long long nX = (long long)S_LEN * HIDDEN;
    split_kernel<<<split_grid(nX), blk>>>(X, Xh, Xl, nX);
    long long nWdq = (long long)HIDDEN * DQ;
    split_kernel<<<split_grid(nWdq), blk>>>(W_dq, Wdqh, Wdql, nWdq);
    long long nWuq = (long long)DQ * NQCR;
    split_kernel<<<split_grid(nWuq), blk>>>(W_uq, Wuqh, Wuql, nWuq);
    long long nWdkv = (long long)HIDDEN * DCKV;
    split_kernel<<<split_grid(nWdkv), blk>>>(W_dkv, Wdkvh, Wdkvl, nWdkv);
    long long nWukv = (long long)DKV * NKV;
    split_kernel<<<split_grid(nWukv), blk>>>(W_ukv, Wukvh, Wukvl, nWukv);
    long long nWo = (long long)NODIM * HIDDEN;
    split_kernel<<<split_grid(nWo), blk>>>(W_o, Woh, Wol, nWo);

    // ---- G1: c_q = X @ W_dq ----
    bgemm3<<<dim3(DQ / 128, S_LEN / 128, 1), blk>>>(
        S_LEN, DQ, HIDDEN, Xh, Xl, HIDDEN, 0, Wdqh, Wdql, DQ, 0, cq, DQ, 0, 1.f);

    rmsnorm_kernel<<<S_LEN, 256>>>(cq, gq, DQ, DQ);
    long long ncq = (long long)S_LEN * DQ;
    split_kernel<<<split_grid(ncq), blk>>>(cq, cqh, cql, ncq);

    // ---- G2: qcr = rmsnorm(c_q) @ W_uq ----
    bgemm3<<<dim3(NQCR / 128, S_LEN / 128, 1), blk>>>(
        S_LEN, NQCR, DQ, cqh, cql, DQ, 0, Wuqh, Wuql, NQCR, 0, qcr, NQCR, 0, 1.f);

    rope_q_kernel<<<(S_LEN * NH) / 8, 256>>>(qcr);
    long long nq = (long long)S_LEN * NQCR;
    split_kernel<<<split_grid(nq), blk>>>(qcr, qh, ql, nq);

    // ---- G3: ckv_kr = X @ W_dkv ----
    bgemm3<<<dim3((DCKV + 127) / 128, S_LEN / 128, 1), blk>>>(
        S_LEN, DCKV, HIDDEN, Xh, Xl, HIDDEN, 0, Wdkvh, Wdkvl, DCKV, 0, ckv, DCKV, 0, 1.f);

    rmsnorm_kernel<<<S_LEN, 256>>>(ckv, gkv, DKV, DCKV);
    rope_k_kernel<<<S_LEN / 8, 256>>>(ckv);
    long long nckv = (long long)S_LEN * DCKV;
    split_kernel<<<split_grid(nckv), blk>>>(ckv, ckvh, ckvl, nckv);

    // ---- G4: kv = rmsnorm(c_kv) @ W_ukv ----
    bgemm3<<<dim3(NKV / 128, S_LEN / 128, 1), blk>>>(
        S_LEN, NKV, DKV, ckvh, ckvl, DCKV, 0, Wukvh, Wukvl, NKV, 0, kv, NKV, 0, 1.f);

    build_kT_split<<<4096, 256>>>(kv, ckv, kTh, kTl);
    long long nkv = (long long)S_LEN * NKV;
    split_kernel<<<split_grid(nkv), blk>>>(kv, kvh, kvl, nkv);

    // ---- G5: scores[h] = Q[h] @ K[h]^T * scale ----
    float scale = 1.0f / sqrtf((float)DQR);
    bgemm3<<<dim3(S_LEN / 128, S_LEN / 128, NH), blk>>>(
        S_LEN, S_LEN, DQR,
        qh, ql, NQCR, (long long)DQR,
        kTh, kTl, S_LEN, (long long)DQR * S_LEN,
        sc, S_LEN, (long long)S_LEN * S_LEN, scale);

    softmax_split_kernel<<<NH * S_LEN, 256>>>(sc, Ph, Pl);

    // ---- G6: O[h] = P[h] @ V[h] ----
    bgemm3<<<dim3(1, S_LEN / 128, NH), blk>>>(
        S_LEN, DH, S_LEN,
        Ph, Pl, S_LEN, (long long)S_LEN * S_LEN,
        kvh + DH, kvl + DH, NKV, (long long)2 * DH,
        ob, NODIM, (long long)DH, 1.f);

    long long no = (long long)S_LEN * NODIM;
    split_kernel<<<split_grid(no), blk>>>(ob, oh, ol, no);

    // ---- G7: out = O @ W_o ----
    bgemm3<<<dim3(HIDDEN / 128, S_LEN / 128, 1), blk>>>(
        S_LEN, HIDDEN, NODIM, oh, ol, NODIM, 0, Woh, Wol, HIDDEN, 0, out, HIDDEN, 0, 1.f);
}

// round 7
// speedup vs baseline: 2.2627x; 1.8475x over previous
#include <cuda_runtime.h>
#include <cuda_bf16.h>
#include <math.h>
#include <stdint.h>
#include <cstdint>

// ---------------------------------------------------------------------------
// MLA forward — bf16x3 GEMMs via mma.sync + cp.async 3-stage pipeline + ldmatrix.
// Shapes: B=1, S=2048, HIDDEN=7168, NH=32, DQ=1536, DKV=512, DH=128, DR=64
// ---------------------------------------------------------------------------

#define S_LEN   2048
#define HIDDEN  7168
#define NH      32
#define DQ      1536
#define DKV     512
#define DH      128
#define DR      64
#define DQR     (DH + DR)            // 192
#define NQCR    (NH * DQR)           // 6144
#define NKV     (NH * 2 * DH)        // 8192
#define DCKV    (DKV + DR)           // 576
#define NODIM   (NH * DH)            // 4096

typedef __nv_bfloat16 bf16;
typedef __nv_bfloat162 bf162;

// ---------------- scratch (device globals; no allocation allowed) ----------
__device__ float g_cq [(long long)S_LEN * DQ];
__device__ float g_qcr[(long long)S_LEN * NQCR];
__device__ float g_ckv[(long long)S_LEN * DCKV];
__device__ float g_kv [(long long)S_LEN * NKV];
__device__ float g_sc [(long long)NH * S_LEN * S_LEN];

__device__ bf16 g_Xh [(long long)S_LEN * HIDDEN],  g_Xl [(long long)S_LEN * HIDDEN];
__device__ bf16 g_Wdqh[(long long)HIDDEN * DQ],    g_Wdql[(long long)HIDDEN * DQ];
__device__ bf16 g_Wuqh[(long long)DQ * NQCR],      g_Wuql[(long long)DQ * NQCR];
__device__ bf16 g_Wdkvh[(long long)HIDDEN * DCKV], g_Wdkvl[(long long)HIDDEN * DCKV];
__device__ bf16 g_Wukvh[(long long)DKV * NKV],     g_Wukvl[(long long)DKV * NKV];
__device__ bf16 g_Woh [(long long)NODIM * HIDDEN], g_Wol [(long long)NODIM * HIDDEN];
__device__ bf16 g_cqh [(long long)S_LEN * DQ],     g_cql [(long long)S_LEN * DQ];
__device__ bf16 g_qh  [(long long)S_LEN * NQCR],   g_ql  [(long long)S_LEN * NQCR];
__device__ bf16 g_ckvh[(long long)S_LEN * DCKV],   g_ckvl[(long long)S_LEN * DCKV];
__device__ bf16 g_kvh [(long long)S_LEN * NKV],    g_kvl [(long long)S_LEN * NKV];
__device__ bf16 g_kTh [(long long)NH * DQR * S_LEN], g_kTl[(long long)NH * DQR * S_LEN];
__device__ bf16 g_Ph  [(long long)NH * S_LEN * S_LEN], g_Pl[(long long)NH * S_LEN * S_LEN];
__device__ bf16 g_oh  [(long long)S_LEN * NODIM],  g_ol [(long long)S_LEN * NODIM];

// ---------------------------------------------------------------------------
__device__ __forceinline__ void split2(float v, bf16& h, bf16& l)
{
    bf16 hh = __float2bfloat16(v);
    h = hh;
    l = __float2bfloat16(v - __bfloat162float(hh));
}

__global__ void split_kernel(const float* __restrict__ s,
                             bf16* __restrict__ h, bf16* __restrict__ l,
                             long long n)
{
    for (long long i = ((long long)blockIdx.x * blockDim.x + threadIdx.x) * 4;
         i < n; i += (long long)gridDim.x * blockDim.x * 4) {
        float4 v = *(const float4*)(s + i);
        bf16 h0,h1,h2,h3,l0,l1,l2,l3;
        split2(v.x,h0,l0); split2(v.y,h1,l1); split2(v.z,h2,l2); split2(v.w,h3,l3);
        *(bf162*)(h + i)     = __halves2bfloat162(h0, h1);
        *(bf162*)(h + i + 2) = __halves2bfloat162(h2, h3);
        *(bf162*)(l + i)     = __halves2bfloat162(l0, l1);
        *(bf162*)(l + i + 2) = __halves2bfloat162(l2, l3);
    }
}

// ---------------------------------------------------------------------------
#define MMA_OP(ac, a, b)                                                     \
    asm volatile("mma.sync.aligned.m16n8k16.row.col.f32.bf16.bf16.f32 "      \
        "{%0,%1,%2,%3}, {%4,%5,%6,%7}, {%8,%9}, {%0,%1,%2,%3};"              \
        : "+f"((ac)[0]), "+f"((ac)[1]), "+f"((ac)[2]), "+f"((ac)[3])         \
        : "r"((a)[0]), "r"((a)[1]), "r"((a)[2]), "r"((a)[3]),                \
          "r"((b)[0]), "r"((b)[1]))

#define CP16(dst, src) \
    asm volatile("cp.async.cg.shared.global [%0], [%1], 16;" :: "r"(dst), "l"(src))
#define CP_COMMIT() asm volatile("cp.async.commit_group;")
#define CP_WAIT1()  asm volatile("cp.async.wait_group 1;")

#define LDSM_X4(f, addr)                                                      \
    asm volatile("ldmatrix.sync.aligned.m8n8.x4.shared.b16 {%0,%1,%2,%3}, [%4];" \
        : "=r"((f)[0]), "=r"((f)[1]), "=r"((f)[2]), "=r"((f)[3]) : "r"(addr))
#define LDSM_X4T(r0, r1, r2, r3, addr)                                        \
    asm volatile("ldmatrix.sync.aligned.m8n8.x4.trans.shared.b16 {%0,%1,%2,%3}, [%4];" \
        : "=r"(r0), "=r"(r1), "=r"(r2), "=r"(r3) : "r"(addr))

// ---------------------------------------------------------------------------
// Batched GEMM, bf16x3 compensated: C = alpha * (Ah·Bh + Ah·Bl + Al·Bh).
// 128x128 tile, BK=32, 3-stage cp.async, 256 threads, 8 warps of 32x64.
// Smem A: [m][k] stride 40 (elems). Smem B: [k][n] stride 136.
// Optional Ch/Cl: hi/lo bf16 split outputs (same ldc/sC).
// Requires: M%128==0, K%32==0, N%8==0, lda/ldb%8==0, base offsets %8==0.
// ---------------------------------------------------------------------------
#define A_ST  (128 * 40)
#define B_ST  (32 * 136)
#define STG   (2 * A_ST + 2 * B_ST)           // elems per stage (18944)
#define SMEM_BYTES (3 * STG * 2)              // 113664 bytes

__global__ __launch_bounds__(256, 1)
void bgemm3(int M, int N, int K,
            const bf16* __restrict__ Ah, const bf16* __restrict__ Al,
            int lda, long long sA,
            const bf16* __restrict__ Bh, const bf16* __restrict__ Bl,
            int ldb, long long sB,
            float* __restrict__ C, bf16* __restrict__ Ch, bf16* __restrict__ Cl,
            int ldc, long long sC, float alpha)
{
    extern __shared__ __align__(16) char dynsmem[];
    uint32_t sbase = (uint32_t)__cvta_generic_to_shared(dynsmem);

    const bf16* pAh = Ah + (long long)blockIdx.z * sA;
    const bf16* pAl = Al + (long long)blockIdx.z * sA;
    const bf16* pBh = Bh + (long long)blockIdx.z * sB;
    const bf16* pBl = Bl + (long long)blockIdx.z * sB;

    const int tid = threadIdx.x;
    const int bm = blockIdx.y << 7;
    const int bn = blockIdx.x << 7;

    const int lane = tid & 31;
    const int warp = tid >> 5;
    const int wm = (warp & 3) << 5;         // 0..96
    const int wn = (warp >> 2) << 6;        // 0, 64
    const int g  = lane >> 2;
    const int qt = (lane & 3) << 1;

    const int nk = K >> 5;                  // BK = 32

    float acc[2][8][4];
#pragma unroll
    for (int i = 0; i < 2; i++)
#pragma unroll
        for (int j = 0; j < 8; j++)
#pragma unroll
            for (int c = 0; c < 4; c++) acc[i][j][c] = 0.f;

    // ---- async stage loader ----
    auto issue_stage = [&](int stg, int k0) {
        uint32_t sb = sbase + (uint32_t)(stg * STG * 2);
#pragma unroll
        for (int r = 0; r < 2; r++) {
            const int c = tid + (r << 8);            // 0..511
            // A: row = c/4, k-chunk = (c%4)*8
            const int arow = c >> 2;
            const int ak   = (c & 3) << 3;
            const long long aoff = (long long)(bm + arow) * lda + k0 + ak;
            const uint32_t dA = sb + (uint32_t)((arow * 40 + ak) * 2);
            CP16(dA,            pAh + aoff);
            CP16(dA + A_ST * 2, pAl + aoff);
            // B: k-row = c/16, n-chunk = (c%16)*8
            const int krow = c >> 4;
            const int nc   = (c & 15) << 3;
            int gn = bn + nc;
            if (gn > N - 8) gn = N - 8;              // clamp (garbage cols masked)
            const long long boff = (long long)(k0 + krow) * ldb + gn;
            const uint32_t dB = sb + (uint32_t)((2 * A_ST + krow * 136 + nc) * 2);
            CP16(dB,            pBh + boff);
            CP16(dB + B_ST * 2, pBl + boff);
        }
    };

    // prologue: stages 0, 1
    issue_stage(0, 0);
    CP_COMMIT();
    if (nk > 1) issue_stage(1, 32);
    CP_COMMIT();

    const int ar  = lane & 15;
    const int hi8 = (lane & 16) >> 1;       // 0 or 8

    for (int kt = 0; kt < nk; kt++) {
        CP_WAIT1();                         // stage kt resident
        __syncthreads();

        if (kt + 2 < nk) issue_stage((kt + 2) % 3, (kt + 2) << 5);
        CP_COMMIT();

        const uint32_t sb = sbase + (uint32_t)((kt % 3) * STG * 2);
        const uint32_t aH = sb;
        const uint32_t aL = sb + A_ST * 2;
        const uint32_t bH = sb + 2 * A_ST * 2;
        const uint32_t bL = sb + (2 * A_ST + B_ST) * 2;

#pragma unroll
        for (int ks = 0; ks < 2; ks++) {
            const int ka = (ks << 4) + hi8;                 // A col (k)
            const uint32_t adr0 = aH + (uint32_t)(((wm + ar) * 40 + ka) * 2);
            uint32_t afH0[4], afH1[4];
            LDSM_X4(afH0, adr0);
            LDSM_X4(afH1, adr0 + 16 * 80);                  // +16 rows

            const int kb = (ks << 4) + ar;                  // B row (k)
            const uint32_t bdr = bH + (uint32_t)((kb * 136 + wn + hi8) * 2);
            uint32_t bfH[8][2];
#pragma unroll
            for (int jp = 0; jp < 4; jp++)
                LDSM_X4T(bfH[2*jp][0], bfH[2*jp][1], bfH[2*jp+1][0], bfH[2*jp+1][1],
                         bdr + jp * 32);

            // pass 1: Ah * Bh
#pragma unroll
            for (int jn = 0; jn < 8; jn++) {
                MMA_OP(acc[0][jn], afH0, bfH[jn]);
                MMA_OP(acc[1][jn], afH1, bfH[jn]);
            }

            // pass 2: Ah * Bl
            const uint32_t bdrL = bL + (uint32_t)((kb * 136 + wn + hi8) * 2);
            uint32_t bfL[8][2];
#pragma unroll
            for (int jp = 0; jp < 4; jp++)
                LDSM_X4T(bfL[2*jp][0], bfL[2*jp][1], bfL[2*jp+1][0], bfL[2*jp+1][1],
                         bdrL + jp * 32);
#pragma unroll
            for (int jn = 0; jn < 8; jn++) {
                MMA_OP(acc[0][jn], afH0, bfL[jn]);
                MMA_OP(acc[1][jn], afH1, bfL[jn]);
            }

            // pass 3: Al * Bh
            const uint32_t adrL = aL + (uint32_t)(((wm + ar) * 40 + ka) * 2);
            uint32_t afL0[4], afL1[4];
            LDSM_X4(afL0, adrL);
            LDSM_X4(afL1, adrL + 16 * 80);
#pragma unroll
            for (int jn = 0; jn < 8; jn++) {
                MMA_OP(acc[0][jn], afL0, bfH[jn]);
                MMA_OP(acc[1][jn], afL1, bfH[jn]);
            }
        }
    }

    // ---- epilogue ----
    float* pC = C ? C + (long long)blockIdx.z * sC : (float*)0;
    bf16* pCh = Ch ? Ch + (long long)blockIdx.z * sC : (bf16*)0;
    bf16* pCl = Cl ? Cl + (long long)blockIdx.z * sC : (bf16*)0;

#pragma unroll
    for (int im = 0; im < 2; im++) {
#pragma unroll
        for (int jn = 0; jn < 8; jn++) {
            const int row = bm + wm + (im << 4) + g;
            const int col = bn + wn + (jn << 3) + qt;
            if (col < N) {
                const float v0 = alpha * acc[im][jn][0];
                const float v1 = alpha * acc[im][jn][1];
                const float v2 = alpha * acc[im][jn][2];
                const float v3 = alpha * acc[im][jn][3];
                if (pC) {
                    *(float2*)(pC + (long long)row * ldc + col) = make_float2(v0, v1);
                    *(float2*)(pC + (long long)(row + 8) * ldc + col) = make_float2(v2, v3);
                }
                if (pCh) {
                    bf16 h0,h1,h2,h3,l0,l1,l2,l3;
                    split2(v0,h0,l0); split2(v1,h1,l1);
                    split2(v2,h2,l2); split2(v3,h3,l3);
                    *(bf162*)(pCh + (long long)row * ldc + col) = __halves2bfloat162(h0, h1);
                    *(bf162*)(pCl + (long long)row * ldc + col) = __halves2bfloat162(l0, l1);
                    *(bf162*)(pCh + (long long)(row + 8) * ldc + col) = __halves2bfloat162(h2, h3);
                    *(bf162*)(pCl + (long long)(row + 8) * ldc + col) = __halves2bfloat162(l2, l3);
                }
            }
        }
    }
}

// ---------------------------------------------------------------------------
// RMSNorm over first W cols (row stride ld), output hi/lo bf16 split.
// ---------------------------------------------------------------------------
__global__ void rmsnorm_split_kernel(const float* __restrict__ x,
                                     const float* __restrict__ g,
                                     int W, int ld,
                                     bf16* __restrict__ oh, bf16* __restrict__ ol)
{
    __shared__ float red[32];
    const float* row = x + (long long)blockIdx.x * ld;
    float s = 0.f;
    for (int i = threadIdx.x; i < W; i += blockDim.x) {
        float v = row[i];
        s += v * v;
    }
#pragma unroll
    for (int o = 16; o; o >>= 1) s += __shfl_xor_sync(0xffffffffu, s, o);
    int w = threadIdx.x >> 5, l = threadIdx.x & 31;
    if (l == 0) red[w] = s;
    __syncthreads();
    if (w == 0) {
        float t = (l < (blockDim.x >> 5)) ? red[l] : 0.f;
#pragma unroll
        for (int o = 16; o; o >>= 1) t += __shfl_xor_sync(0xffffffffu, t, o);
        if (l == 0) red[0] = t;
    }
    __syncthreads();
    float scale = rsqrtf(red[0] / (float)W + 1.1920929e-07f);
    bf16* ohr = oh + (long long)blockIdx.x * ld;
    bf16* olr = ol + (long long)blockIdx.x * ld;
    for (int i = threadIdx.x; i < W; i += blockDim.x) {
        bf16 hh, ll;
        split2(row[i] * scale * g[i], hh, ll);
        ohr[i] = hh;
        olr[i] = ll;
    }
}

// ---------------------------------------------------------------------------
// RoPE (D=64)
// ---------------------------------------------------------------------------
__device__ __forceinline__ void rope_pair(float* base, int j, int t)
{
    float ex  = (2.0f * (float)j) / 64.0f;
    float inv = 1.0f / powf(10000.0f, ex);
    float fr  = (float)t * inv;
    float c   = cosf(fr);
    float sn  = sinf(fr);
    float x1 = base[j];
    float x2 = base[j + 32];
    base[j]      = x1 * c - x2 * sn;
    base[j + 32] = x2 * c + x1 * sn;
}

__global__ void rope_q_kernel(float* __restrict__ qcr)
{
    int item = blockIdx.x * (blockDim.x >> 5) + (threadIdx.x >> 5);
    if (item >= S_LEN * NH) return;
    int s = item >> 5;
    int h = item & 31;
    int j = threadIdx.x & 31;
    rope_pair(qcr + (long long)s * NQCR + h * DQR + DH, j, s);
}

// rope on ckv cols 512..575, fp32 in place + hi/lo split out
__global__ void rope_k_kernel(float* __restrict__ ckv,
                              bf16* __restrict__ oh, bf16* __restrict__ ol)
{
    int item = blockIdx.x * (blockDim.x >> 5) + (threadIdx.x >> 5);
    if (item >= S_LEN) return;
    int j = threadIdx.x & 31;
    float* base = ckv + (long long)item * DCKV + DKV;
    rope_pair(base, j, item);
    bf16 hh, ll;
    split2(base[j], hh, ll);
    oh[(long long)item * DCKV + DKV + j] = hh;
    ol[(long long)item * DCKV + DKV + j] = ll;
    split2(base[j + 32], hh, ll);
    oh[(long long)item * DCKV + DKV + j + 32] = hh;
    ol[(long long)item * DCKV + DKV + j + 32] = ll;
}

// ---------------------------------------------------------------------------
// kT[h][d][s] hi/lo from fp32 kv + roped ckv.
// ---------------------------------------------------------------------------
__global__ void build_kT_split(const float* __restrict__ kv,
                               const float* __restrict__ ckv,
                               bf16* __restrict__ kTh, bf16* __restrict__ kTl)
{
    const long long total = (long long)NH * DQR * S_LEN;
    for (long long i = (long long)blockIdx.x * blockDim.x + threadIdx.x;
         i < total; i += (long long)gridDim.x * blockDim.x) {
        int s = (int)(i % S_LEN);
        long long t = i / S_LEN;
        int d = (int)(t % DQR);
        int h = (int)(t / DQR);
        float v;
        if (d < DH) v = kv[(long long)s * NKV + h * 2 * DH + d];
        else        v = ckv[(long long)s * DCKV + DKV + (d - DH)];
        bf16 hh, ll;
        split2(v, hh, ll);
        kTh[i] = hh;
        kTl[i] = ll;
    }
}

// ---------------------------------------------------------------------------
// Row softmax (width 2048) + hi/lo split output.
// ---------------------------------------------------------------------------
__global__ void softmax_split_kernel(float* __restrict__ sc,
                                     bf16* __restrict__ ph, bf16* __restrict__ pl)
{
    __shared__ float red[32];
    float* row = sc + (long long)blockIdx.x * S_LEN;
    bf16* hrow = ph + (long long)blockIdx.x * S_LEN;
    bf16* lrow = pl + (long long)blockIdx.x * S_LEN;
    int w = threadIdx.x >> 5, l = threadIdx.x & 31;

    float m = -3.402823466e+38f;
    for (int i = threadIdx.x; i < S_LEN; i += blockDim.x)
        m = fmaxf(m, row[i]);
#pragma unroll
    for (int o = 16; o; o >>= 1) m = fmaxf(m, __shfl_xor_sync(0xffffffffu, m, o));
    if (l == 0) red[w] = m;
    __syncthreads();
    if (w == 0) {
        float t = (l < (blockDim.x >> 5)) ? red[l] : -3.402823466e+38f;
#pragma unroll
        for (int o = 16; o; o >>= 1) t = fmaxf(t, __shfl_xor_sync(0xffffffffu, t, o));
        if (l == 0) red[0] = t;
    }
    __syncthreads();
    float M = red[0];
    __syncthreads();

    float s = 0.f;
    for (int i = threadIdx.x; i < S_LEN; i += blockDim.x) {
        float e = expf(row[i] - M);
        row[i] = e;
        s += e;
    }
#pragma unroll
    for (int o = 16; o; o >>= 1) s += __shfl_xor_sync(0xffffffffu, s, o);
    if (l == 0) red[w] = s;
    __syncthreads();
    if (w == 0) {
        float t = (l < (blockDim.x >> 5)) ? red[l] : 0.f;
#pragma unroll
        for (int o = 16; o; o >>= 1) t += __shfl_xor_sync(0xffffffffu, t, o);
        if (l == 0) red[0] = t;
    }
    __syncthreads();
    float inv = 1.0f / red[0];
    for (int i = threadIdx.x; i < S_LEN; i += blockDim.x) {
        bf16 hh, ll;
        split2(row[i] * inv, hh, ll);
        hrow[i] = hh;
        lrow[i] = ll;
    }
}

// ---------------------------------------------------------------------------
static inline int split_grid(long long n)
{
    long long b = (n / 4 + 255) / 256;
    if (b > 8192) b = 8192;
    return (int)b;
}

extern "C" void kernel_launch(void* const* d_in, const int* in_sizes, int n_in,
                              void* d_out, int out_size)
{
    const float* X     = (const float*)d_in[0];
    const float* W_dq  = (const float*)d_in[1];
    const float* gq    = (const float*)d_in[2];
    const float* W_uq  = (const float*)d_in[3];
    const float* W_dkv = (const float*)d_in[4];
    const float* gkv   = (const float*)d_in[5];
    const float* W_ukv = (const float*)d_in[6];
    const float* W_o   = (const float*)d_in[7];
    float* out = (float*)d_out;

    float *cq, *qcr, *ckv, *kv, *sc;
    bf16 *Xh,*Xl,*Wdqh,*Wdql,*Wuqh,*Wuql,*Wdkvh,*Wdkvl,*Wukvh,*Wukvl,*Woh,*Wol;
    bf16 *cqh,*cql,*qh,*ql,*ckvh,*ckvl,*kvh,*kvl,*kTh,*kTl,*Ph,*Pl,*oh,*ol;

    cudaGetSymbolAddress((void**)&cq,  g_cq);
    cudaGetSymbolAddress((void**)&qcr, g_qcr);
    cudaGetSymbolAddress((void**)&ckv, g_ckv);
    cudaGetSymbolAddress((void**)&kv,  g_kv);
    cudaGetSymbolAddress((void**)&sc,  g_sc);
    cudaGetSymbolAddress((void**)&Xh,  g_Xh);   cudaGetSymbolAddress((void**)&Xl,  g_Xl);
    cudaGetSymbolAddress((void**)&Wdqh, g_Wdqh);  cudaGetSymbolAddress((void**)&Wdql, g_Wdql);
    cudaGetSymbolAddress((void**)&Wuqh, g_Wuqh);  cudaGetSymbolAddress((void**)&Wuql, g_Wuql);
    cudaGetSymbolAddress((void**)&Wdkvh, g_Wdkvh); cudaGetSymbolAddress((void**)&Wdkvl, g_Wdkvl);
    cudaGetSymbolAddress((void**)&Wukvh, g_Wukvh); cudaGetSymbolAddress((void**)&Wukvl, g_Wukvl);
    cudaGetSymbolAddress((void**)&Woh, g_Woh);   cudaGetSymbolAddress((void**)&Wol, g_Wol);
    cudaGetSymbolAddress((void**)&cqh, g_cqh);   cudaGetSymbolAddress((void**)&cql, g_cql);
    cudaGetSymbolAddress((void**)&qh,  g_qh);    cudaGetSymbolAddress((void**)&ql,  g_ql);
    cudaGetSymbolAddress((void**)&ckvh, g_ckvh); cudaGetSymbolAddress((void**)&ckvl, g_ckvl);
    cudaGetSymbolAddress((void**)&kvh, g_kvh);   cudaGetSymbolAddress((void**)&kvl, g_kvl);
    cudaGetSymbolAddress((void**)&kTh, g_kTh);   cudaGetSymbolAddress((void**)&kTl, g_kTl);
    cudaGetSymbolAddress((void**)&Ph,  g_Ph);    cudaGetSymbolAddress((void**)&Pl,  g_Pl);
    cudaGetSymbolAddress((void**)&oh,  g_oh);    cudaGetSymbolAddress((void**)&ol,  g_ol);

    cudaFuncSetAttribute(bgemm3, cudaFuncAttributeMaxDynamicSharedMemorySize, SMEM_BYTES);

    dim3 blk(256);
    const int SB = SMEM_BYTES;

    // ---- split inputs to bf16 hi/lo ----
    long long nX = (long long)S_LEN * HIDDEN;
    split_kernel<<<split_grid(nX), blk>>>(X, Xh, Xl, nX);
    long long nWdq = (long long)HIDDEN * DQ;
    split_kernel<<<split_grid(nWdq), blk>>>(W_dq, Wdqh, Wdql, nWdq);
    long long nWuq = (long long)DQ * NQCR;
    split_kernel<<<split_grid(nWuq), blk>>>(W_uq, Wuqh, Wuql, nWuq);
    long long nWdkv = (long long)HIDDEN * DCKV;
    split_kernel<<<split_grid(nWdkv), blk>>>(W_dkv, Wdkvh, Wdkvl, nWdkv);
    long long nWukv = (long long)DKV * NKV;
    split_kernel<<<split_grid(nWukv), blk>>>(W_ukv, Wukvh, Wukvl, nWukv);
    long long nWo = (long long)NODIM * HIDDEN;
    split_kernel<<<split_grid(nWo), blk>>>(W_o, Woh, Wol, nWo);

    // ---- G1: c_q = X @ W_dq ----
    bgemm3<<<dim3(DQ / 128, S_LEN / 128, 1), blk, SB>>>(
        S_LEN, DQ, HIDDEN, Xh, Xl, HIDDEN, 0, Wdqh, Wdql, DQ, 0,
        cq, (bf16*)0, (bf16*)0, DQ, 0, 1.f);

    // rmsnorm + split
    rmsnorm_split_kernel<<<S_LEN, 256>>>(cq, gq, DQ, DQ, cqh, cql);

    // ---- G2: qcr = rmsnorm(c_q) @ W_uq ----
    bgemm3<<<dim3(NQCR / 128, S_LEN / 128, 1), blk, SB>>>(
        S_LEN, NQCR, DQ, cqh, cql, DQ, 0, Wuqh, Wuql, NQCR, 0,
        qcr, (bf16*)0, (bf16*)0, NQCR, 0, 1.f);

    rope_q_kernel<<<(S_LEN * NH) / 8, 256>>>(qcr);
    long long nq = (long long)S_LEN * NQCR;
    split_kernel<<<split_grid(nq), blk>>>(qcr, qh, ql, nq);

    // ---- G3: ckv_kr = X @ W_dkv ----
    bgemm3<<<dim3((DCKV + 127) / 128, S_LEN / 128, 1), blk, SB>>>(
        S_LEN, DCKV, HIDDEN, Xh, Xl, HIDDEN, 0, Wdkvh, Wdkvl, DCKV, 0,
        ckv, (bf16*)0, (bf16*)0, DCKV, 0, 1.f);

    rmsnorm_split_kernel<<<S_LEN, 256>>>(ckv, gkv, DKV, DCKV, ckvh, ckvl);
    rope_k_kernel<<<S_LEN / 8, 256>>>(ckv, ckvh, ckvl);

    // ---- G4: kv = rmsnorm(c_kv) @ W_ukv (epilogue emits fp32 + hi/lo) ----
    bgemm3<<<dim3(NKV / 128, S_LEN / 128, 1), blk, SB>>>(
        S_LEN, NKV, DKV, ckvh, ckvl, DCKV, 0, Wukvh, Wukvl, NKV, 0,
        kv, kvh, kvl, NKV, 0, 1.f);

    build_kT_split<<<4096, 256>>>(kv, ckv, kTh, kTl);

    // ---- G5: scores[h] = Q[h] @ K[h]^T * scale ----
    float scale = 1.0f / sqrtf((float)DQR);
    bgemm3<<<dim3(S_LEN / 128, S_LEN / 128, NH), blk, SB>>>(
        S_LEN, S_LEN, DQR,
        qh, ql, NQCR, (long long)DQR,
        kTh, kTl, S_LEN, (long long)DQR * S_LEN,
        sc, (bf16*)0, (bf16*)0, S_LEN, (long long)S_LEN * S_LEN, scale);

    softmax_split_kernel<<<NH * S_LEN, 256>>>(sc, Ph, Pl);

    // ---- G6: O[h] = P[h] @ V[h] (epilogue emits hi/lo only) ----
    bgemm3<<<dim3(1, S_LEN / 128, NH), blk, SB>>>(
        S_LEN, DH, S_LEN,
        Ph, Pl, S_LEN, (long long)S_LEN * S_LEN,
        kvh + DH, kvl + DH, NKV, (long long)2 * DH,
        (float*)0, oh, ol, NODIM, (long long)DH, 1.f);

    // ---- G7: out = O @ W_o ----
    bgemm3<<<dim3(HIDDEN / 128, S_LEN / 128, 1), blk, SB>>>(
        S_LEN, HIDDEN, NODIM, oh, ol, NODIM, 0, Woh, Wol, HIDDEN, 0,
        out, (bf16*)0, (bf16*)0, HIDDEN, 0, 1.f);
}